// round 12
// baseline (speedup 1.0000x reference)
#include <cuda_runtime.h>
#include <cuda_fp16.h>
#include <mma.h>
using namespace nvcuda;

#define DF   64
#define NN   100000
#define EE   1600000
#define EEP  (EE + 8 * NN)           // padded CSR capacity (rows padded to 8)
#define EPSV 1e-5f
#define WSCALE 268435456.0f          // 2^28 fixed-point weight scale
#define WINV   (1.0f / 268435456.0f)
#define NCLS 16                      // degree classes (windows = paddeg/8)

// ---------------- scratch (device globals; zero-initialized at load) -------
// Invariant: every call leaves g_degcnt/g_bnsum/g_bnsq/g_scan_ctr/g_clscnt/
// g_clsfill all-zero (CLEAN tail in the final kernel), matching first-call
// zero-init. Everything else is fully rewritten every call.
__device__ unsigned long long g_degcnt[NN]; // (cnt<<48) | fx28 weighted degree
__device__ float g_dinv[NN];
__device__ int   g_fill[NN];                // scan seeds with prefix; fill bumps
__device__ int   g_rowptr[NN + 1];          // padded exclusive prefix
__device__ unsigned long long g_edge[EEP];  // packed: (w_bits<<32) | src
__device__ __half g_h1[(size_t)NN * DF];    // dinv-scaled layer-1 features (fp16)
__device__ __half g_hb[(size_t)NN * DF];    // aggregated layer-1 output (fp16)
__device__ __half g_h2[(size_t)NN * DF];    // dinv-scaled layer-2 features (fp16)
__device__ float g_bnsum[DF];
__device__ float g_bnsq[DF];
__device__ int   g_part[128];
__device__ int   g_scan_ctr;
__device__ int   g_clscnt[NCLS];            // per-degree-class node counts
__device__ int   g_clsfill[NCLS];           // scatter cursors
__device__ int   g_perm[NN];                // degree-class-sorted node order

__device__ __forceinline__ unsigned long long pack_dc(float w) {
    return (1ULL << 48) | (unsigned long long)(fmaf(w, WSCALE, 0.5f));
}

// ---------------- edge pass 1: single packed atomic per edge, 8/thread -----
__global__ void k_edge_deg(const int* __restrict__ ei,
                           const float* __restrict__ w, int E) {
    int e8 = (blockIdx.x * blockDim.x + threadIdx.x) * 8;
    if (e8 + 7 < E) {
        int4   d0 = *(const int4*)&ei[E + e8];
        int4   d1 = *(const int4*)&ei[E + e8 + 4];
        float4 w0 = *(const float4*)&w[e8];
        float4 w1 = *(const float4*)&w[e8 + 4];
        atomicAdd(&g_degcnt[d0.x], pack_dc(w0.x));
        atomicAdd(&g_degcnt[d0.y], pack_dc(w0.y));
        atomicAdd(&g_degcnt[d0.z], pack_dc(w0.z));
        atomicAdd(&g_degcnt[d0.w], pack_dc(w0.w));
        atomicAdd(&g_degcnt[d1.x], pack_dc(w1.x));
        atomicAdd(&g_degcnt[d1.y], pack_dc(w1.y));
        atomicAdd(&g_degcnt[d1.z], pack_dc(w1.z));
        atomicAdd(&g_degcnt[d1.w], pack_dc(w1.w));
    } else {
        for (int e = e8; e < E; e++)
            atomicAdd(&g_degcnt[ei[E + e]], pack_dc(w[e]));
    }
}

// ---------------- fused scan: dinv + padded prefix + class histogram -------
__global__ void k_scan(int n, int nb) {
    __shared__ int s[1024];
    __shared__ int sp[128];
    int t = threadIdx.x;
    int i = blockIdx.x * 1024 + t;

    int cnt = 0, v = 0;
    if (i < n) {
        unsigned long long p = g_degcnt[i];
        cnt = (int)(p >> 48);
        float deg = (float)(long long)(p & 0xFFFFFFFFFFFFULL) * WINV;
        g_dinv[i] = rsqrtf(deg + 1.0f);        // +1 = self loop
        v = (cnt + 7) & ~7;                    // pad row to multiple of 8
        int wc = v >> 3; if (wc > NCLS - 1) wc = NCLS - 1;
        atomicAdd(&g_clscnt[wc], 1);           // published by the fence below
    }

    s[t] = v;
    __syncthreads();
    for (int off = 512; off > 0; off >>= 1) {
        if (t < off) s[t] += s[t + off];
        __syncthreads();
    }
    if (t == 0) {
        g_part[blockIdx.x] = s[0];
        __threadfence();
        atomicAdd(&g_scan_ctr, 1);
    }
    __syncthreads();

    s[t] = v;
    __syncthreads();
    for (int off = 1; off < 1024; off <<= 1) {
        int a = (t >= off) ? s[t - off] : 0;
        __syncthreads();
        s[t] += a;
        __syncthreads();
    }

    if (t == 0) {
        while (atomicAdd(&g_scan_ctr, 0) < nb) { }
    }
    __syncthreads();

    if (t < 128) sp[t] = (t < nb) ? g_part[t] : 0;
    __syncthreads();
    #pragma unroll
    for (int off = 1; off < 128; off <<= 1) {
        int a = (t < 128 && t >= off) ? sp[t - off] : 0;
        __syncthreads();
        if (t < 128) sp[t] += a;
        __syncthreads();
    }

    int bp = (blockIdx.x > 0) ? sp[blockIdx.x - 1] : 0;
    if (i < n) {
        int p = bp + s[t] - v;                 // padded exclusive prefix
        g_rowptr[i] = p;
        g_fill[i]   = p;                       // seed fill cursor
        for (int k = p + cnt; k < p + v; k++)  // zero-weight pad slots
            g_edge[k] = 0ULL;
    }
    if (i == n - 1) g_rowptr[n] = bp + s[t];
}

// ---------------- perm build: degree-class counting-sort scatter -----------
// Runs after k_scan (stream-ordered); produces g_perm so that consecutive
// perm entries have equal window counts -> divergence-free agg warps.
__global__ void k_perm(int n) {
    __shared__ int off[NCLS];
    if (threadIdx.x == 0) {
        int a = 0;
        #pragma unroll
        for (int c = 0; c < NCLS; c++) { off[c] = a; a += g_clscnt[c]; }
    }
    __syncthreads();
    int i = blockIdx.x * blockDim.x + threadIdx.x;
    if (i < n) {
        int v = g_rowptr[i + 1] - g_rowptr[i];
        int wc = v >> 3; if (wc > NCLS - 1) wc = NCLS - 1;
        int pos = off[wc] + atomicAdd(&g_clsfill[wc], 1);
        g_perm[pos] = i;
    }
}

// ---------------- edge pass 2: fill CSR (raw weight; no gathers), 4/thr ----
__device__ __forceinline__ unsigned long long pack_edge(float w, int s) {
    return ((unsigned long long)__float_as_uint(w) << 32) |
           (unsigned long long)(unsigned)s;
}
__global__ void k_fill(const int* __restrict__ ei,
                       const float* __restrict__ w, int E) {
    int e4 = (blockIdx.x * blockDim.x + threadIdx.x) * 4;
    if (e4 + 3 < E) {
        int4   sv = *(const int4*)&ei[e4];
        int4   dv = *(const int4*)&ei[E + e4];
        float4 wv = *(const float4*)&w[e4];
        int s0 = atomicAdd(&g_fill[dv.x], 1);
        int s1 = atomicAdd(&g_fill[dv.y], 1);
        int s2 = atomicAdd(&g_fill[dv.z], 1);
        int s3 = atomicAdd(&g_fill[dv.w], 1);
        g_edge[s0] = pack_edge(wv.x, sv.x);
        g_edge[s1] = pack_edge(wv.y, sv.y);
        g_edge[s2] = pack_edge(wv.z, sv.z);
        g_edge[s3] = pack_edge(wv.w, sv.w);
    } else {
        for (int e = e4; e < E; e++) {
            int slot = atomicAdd(&g_fill[ei[E + e]], 1);
            g_edge[slot] = pack_edge(w[e], ei[e]);
        }
    }
}

// ---------------- GEMM (tensor cores): Yh = dinv .* (f(X) @ W), fp16 out ---
template <bool BN, bool HALF_IN>
__global__ void __launch_bounds__(256) k_gemm(const void* __restrict__ Xv,
                                              const float* __restrict__ W,
                                              __half* __restrict__ Yh, int n,
                                              const float* __restrict__ gamma,
                                              const float* __restrict__ beta,
                                              float invn) {
    __shared__ __align__(16) char usm[128 * 68 * 4];     // 34 KB union A/C
    __shared__ __align__(16) __half sB[64][72];          // 9 KB W fp16
    __shared__ float sBNa[64], sBNc[64];
    __half (*sA)[72] = (__half(*)[72])usm;
    float  (*uC)[68] = (float(*)[68])usm;

    int tid  = threadIdx.x;
    int w    = tid >> 5;
    int lane = tid & 31;
    int rbase = blockIdx.x * 128;

    if (BN && tid < 64) {
        float mu   = g_bnsum[tid] * invn;
        float var  = g_bnsq[tid] * invn - mu * mu;
        float a    = gamma[tid] * rsqrtf(var + EPSV);
        sBNa[tid] = a;
        sBNc[tid] = beta[tid] - mu * a;
    }
    for (int idx = tid; idx < 64 * 16; idx += 256) {
        int r = idx >> 4, c4 = idx & 15;
        float4 v = ((const float4*)W)[idx];
        __half2 h0 = __floats2half2_rn(v.x, v.y);
        __half2 h1 = __floats2half2_rn(v.z, v.w);
        *(__half2*)&sB[r][c4 * 4]     = h0;
        *(__half2*)&sB[r][c4 * 4 + 2] = h1;
    }
    if (BN) __syncthreads();

    if (HALF_IN) {
        const __half* X = (const __half*)Xv;
        for (int idx = tid; idx < 128 * 8; idx += 256) {
            int r = idx >> 3, c8 = idx & 7;
            int gr = rbase + r;
            uint4 v = (gr < n) ? ((const uint4*)X)[(size_t)gr * 8 + c8]
                               : make_uint4(0, 0, 0, 0);
            if (BN) {
                #pragma unroll
                for (int q = 0; q < 4; q++) {
                    unsigned lo = (&v.x)[q];
                    float2 f = __half22float2(*(const __half2*)&lo);
                    int c = c8 * 8 + q * 2;
                    f.x = fmaxf(fmaf(sBNa[c],     f.x, sBNc[c]),     0.f);
                    f.y = fmaxf(fmaf(sBNa[c + 1], f.y, sBNc[c + 1]), 0.f);
                    __half2 h = __floats2half2_rn(f.x, f.y);
                    (&v.x)[q] = *(unsigned*)&h;
                }
            }
            *(uint4*)&sA[r][c8 * 8] = v;
        }
    } else {
        const float* X = (const float*)Xv;
        for (int idx = tid; idx < 128 * 16; idx += 256) {
            int r = idx >> 4, c4 = idx & 15;
            int gr = rbase + r;
            float4 v = (gr < n) ? ((const float4*)X)[(size_t)gr * 16 + c4]
                                : make_float4(0.f, 0.f, 0.f, 0.f);
            if (BN) {
                int c = c4 * 4;
                v.x = fmaxf(fmaf(sBNa[c],     v.x, sBNc[c]),     0.f);
                v.y = fmaxf(fmaf(sBNa[c + 1], v.y, sBNc[c + 1]), 0.f);
                v.z = fmaxf(fmaf(sBNa[c + 2], v.z, sBNc[c + 2]), 0.f);
                v.w = fmaxf(fmaf(sBNa[c + 3], v.w, sBNc[c + 3]), 0.f);
            }
            __half2 h0 = __floats2half2_rn(v.x, v.y);
            __half2 h1 = __floats2half2_rn(v.z, v.w);
            *(__half2*)&sA[r][c4 * 4]     = h0;
            *(__half2*)&sA[r][c4 * 4 + 2] = h1;
        }
    }
    __syncthreads();

    wmma::fragment<wmma::matrix_a, 16, 16, 16, __half, wmma::row_major> af[4];
    #pragma unroll
    for (int kt = 0; kt < 4; kt++)
        wmma::load_matrix_sync(af[kt], &sA[w * 16][kt * 16], 72);
    __syncthreads();   // all A frags resident; usm may now be reused as C

    #pragma unroll
    for (int nt = 0; nt < 4; nt++) {
        wmma::fragment<wmma::accumulator, 16, 16, 16, float> cf;
        wmma::fill_fragment(cf, 0.0f);
        #pragma unroll
        for (int kt = 0; kt < 4; kt++) {
            wmma::fragment<wmma::matrix_b, 16, 16, 16, __half, wmma::row_major> bf;
            wmma::load_matrix_sync(bf, &sB[kt * 16][nt * 16], 72);
            wmma::mma_sync(cf, af[kt], bf, cf);
        }
        wmma::store_matrix_sync(&uC[w * 16][nt * 16], cf, 68, wmma::mem_row_major);
    }
    __syncwarp();

    int rl = lane & 15;
    int ch = lane >> 4;
    int r  = rbase + w * 16 + rl;
    if (r < n) {
        float dv = g_dinv[r];
        const float* crow = &uC[w * 16 + rl][ch * 32];
        uint4* dst = (uint4*)(Yh + (size_t)r * 64 + ch * 32);
        #pragma unroll
        for (int g = 0; g < 4; g++) {
            __half2 h0 = __floats2half2_rn(crow[8*g + 0] * dv, crow[8*g + 1] * dv);
            __half2 h1 = __floats2half2_rn(crow[8*g + 2] * dv, crow[8*g + 3] * dv);
            __half2 h2 = __floats2half2_rn(crow[8*g + 4] * dv, crow[8*g + 5] * dv);
            __half2 h3 = __floats2half2_rn(crow[8*g + 6] * dv, crow[8*g + 7] * dv);
            uint4 st;
            st.x = *(unsigned*)&h0; st.y = *(unsigned*)&h1;
            st.z = *(unsigned*)&h2; st.w = *(unsigned*)&h3;
            dst[g] = st;
        }
    }
}

// ---------------- aggregation: 8 lanes/node, degree-class scheduled --------
// Node slots map through g_perm so the 4 nodes of a warp (and the 32 of a
// block) have equal window counts -> no divergence straggling.
template <bool STATS, bool CLEAN, bool HALF_OUT>
__global__ void __launch_bounds__(256, 3) k_agg(const __half* __restrict__ H,
                                                const float* __restrict__ bias,
                                                void* __restrict__ outv, int n) {
    int tid = threadIdx.x;
    int sub = tid >> 3;         // 0..31 node slot
    int l8  = tid & 7;          // feature group (8 halves = 16B)
    int slot = blockIdx.x * 32 + sub;
    int i = (slot < n) ? g_perm[slot] : -1;

    float acc[8];
    #pragma unroll
    for (int k = 0; k < 8; k++) acc[k] = 0.0f;

    if (i >= 0) {
        {   // self term (weight 1 in the dinv-scaled domain)
            uint4 u = ((const uint4*)(H + (size_t)i * 64))[l8];
            float2 f0 = __half22float2(*(const __half2*)&u.x);
            float2 f1 = __half22float2(*(const __half2*)&u.y);
            float2 f2 = __half22float2(*(const __half2*)&u.z);
            float2 f3 = __half22float2(*(const __half2*)&u.w);
            acc[0] = f0.x; acc[1] = f0.y; acc[2] = f1.x; acc[3] = f1.y;
            acc[4] = f2.x; acc[5] = f2.y; acc[6] = f3.x; acc[7] = f3.y;
        }

        int e   = g_rowptr[i];
        int end = g_rowptr[i + 1];   // e, end multiples of 8

        for (int base = e; base < end; base += 8) {
            const ulonglong2* pp = (const ulonglong2*)(g_edge + base);
            ulonglong2 q0 = pp[0], q1 = pp[1], q2 = pp[2], q3 = pp[3];
            unsigned long long p[8] = { q0.x, q0.y, q1.x, q1.y,
                                        q2.x, q2.y, q3.x, q3.y };
            uint4 u[8];
            #pragma unroll
            for (int j = 0; j < 8; j++)
                u[j] = ((const uint4*)(H + (size_t)(unsigned)p[j] * 64))[l8];
            #pragma unroll
            for (int j = 0; j < 8; j++) {
                float wj = __uint_as_float((unsigned)(p[j] >> 32));
                #pragma unroll
                for (int q = 0; q < 4; q++) {
                    unsigned lo = (&u[j].x)[q];
                    float2 f = __half22float2(*(const __half2*)&lo);
                    acc[2*q]   = fmaf(wj, f.x, acc[2*q]);
                    acc[2*q+1] = fmaf(wj, f.y, acc[2*q+1]);
                }
            }
        }

        float dv = g_dinv[i];
        const float4* B4 = (const float4*)bias;
        float4 b0 = B4[l8 * 2], b1 = B4[l8 * 2 + 1];
        #pragma unroll
        for (int k = 0; k < 4; k++) acc[k]     = fmaf(dv, acc[k],     (&b0.x)[k]);
        #pragma unroll
        for (int k = 0; k < 4; k++) acc[k + 4] = fmaf(dv, acc[k + 4], (&b1.x)[k]);

        if (HALF_OUT) {
            __half* out = (__half*)outv;
            __half2 h0 = __floats2half2_rn(acc[0], acc[1]);
            __half2 h1 = __floats2half2_rn(acc[2], acc[3]);
            __half2 h2 = __floats2half2_rn(acc[4], acc[5]);
            __half2 h3 = __floats2half2_rn(acc[6], acc[7]);
            uint4 st;
            st.x = *(unsigned*)&h0; st.y = *(unsigned*)&h1;
            st.z = *(unsigned*)&h2; st.w = *(unsigned*)&h3;
            ((uint4*)(out + (size_t)i * 64))[l8] = st;
        } else {
            float* out = (float*)outv;
            float4* O4 = (float4*)(out + (size_t)i * 64);
            O4[l8 * 2]     = make_float4(acc[0], acc[1], acc[2], acc[3]);
            O4[l8 * 2 + 1] = make_float4(acc[4], acc[5], acc[6], acc[7]);
        }
    }

    if (STATS) {
        __shared__ __align__(16) float sacc[32][68];
        float4* row = (float4*)&sacc[sub][l8 * 8];
        row[0] = make_float4(acc[0], acc[1], acc[2], acc[3]);
        row[1] = make_float4(acc[4], acc[5], acc[6], acc[7]);
        __syncthreads();
        if (tid < 64) {
            float s = 0.f, q = 0.f;
            #pragma unroll
            for (int k = 0; k < 32; k++) {
                float v = sacc[k][tid];
                s += v;
                q += v * v;
            }
            atomicAdd(&g_bnsum[tid], s);
            atomicAdd(&g_bnsq[tid],  q);
        }
    }

    if (CLEAN) {
        int g = blockIdx.x * 256 + tid;
        if (g < n) g_degcnt[g] = 0ULL;
        if (g < DF) { g_bnsum[g] = 0.0f; g_bnsq[g] = 0.0f; }
        if (g < NCLS) { g_clscnt[g] = 0; g_clsfill[g] = 0; }
        if (g == 0) g_scan_ctr = 0;
    }
}

// ---------------------------------------------------------------------------
// Fork resources: created once on the first (uncaptured correctness) call.
static cudaStream_t g_s2  = nullptr;
static cudaEvent_t  g_ev1 = nullptr;
static cudaEvent_t  g_ev2 = nullptr;

extern "C" void kernel_launch(void* const* d_in, const int* in_sizes, int n_in,
                              void* d_out, int out_size) {
    const float* x     = (const float*)d_in[0];
    const int*   ei    = (const int*)d_in[1];
    const float* ew    = (const float*)d_in[2];
    const float* W1    = (const float*)d_in[3];
    const float* b1    = (const float*)d_in[4];
    const float* gamma = (const float*)d_in[5];
    const float* beta  = (const float*)d_in[6];
    const float* W2    = (const float*)d_in[7];
    const float* b2    = (const float*)d_in[8];

    int N = in_sizes[0] / DF;
    int E = in_sizes[2];
    if (N > NN || E > EE) return;

    if (!g_s2) {
        cudaStreamCreateWithFlags(&g_s2, cudaStreamNonBlocking);
        cudaEventCreateWithFlags(&g_ev1, cudaEventDisableTiming);
        cudaEventCreateWithFlags(&g_ev2, cudaEventDisableTiming);
    }

    __half *p_h1, *p_hb, *p_h2;
    cudaGetSymbolAddress((void**)&p_h1, g_h1);
    cudaGetSymbolAddress((void**)&p_hb, g_hb);
    cudaGetSymbolAddress((void**)&p_h2, g_h2);

    int nb = (N + 1023) / 1024;
    float invn = 1.0f / (float)N;

    // ---- CSR build chain (stream 0) ----
    k_edge_deg<<<(E / 8 + 255) / 256 + 1, 256>>>(ei, ew, E);
    k_scan<<<nb, 1024>>>(N, nb);

    // ---- fork: perm build + GEMM1 (need only scan output) overlap fill ----
    cudaEventRecord(g_ev1, 0);
    cudaStreamWaitEvent(g_s2, g_ev1, 0);
    k_perm<<<(N + 255) / 256, 256, 0, g_s2>>>(N);
    k_gemm<false, false><<<(N + 127) / 128, 256, 0, g_s2>>>(
        x, W1, p_h1, N, nullptr, nullptr, 0.f);
    cudaEventRecord(g_ev2, g_s2);

    k_fill<<<(E / 4 + 255) / 256 + 1, 256>>>(ei, ew, E);

    cudaStreamWaitEvent(0, g_ev2, 0);   // join before agg1

    // ---- serial tail (data-dependent) ----
    k_agg<true, false, true><<<(N + 31) / 32, 256>>>(p_h1, b1, p_hb, N);
    k_gemm<true, true><<<(N + 127) / 128, 256>>>(
        p_hb, W2, p_h2, N, gamma, beta, invn);
    k_agg<false, true, false><<<(N + 31) / 32, 256>>>(p_h2, b2, d_out, N);
}

// round 13
// speedup vs baseline: 1.4486x; 1.4486x over previous
#include <cuda_runtime.h>
#include <cuda_fp16.h>
#include <mma.h>
using namespace nvcuda;

#define DF   64
#define NN   100000
#define EE   1600000
#define EEP  (EE + 8 * NN)           // padded CSR capacity (rows padded to 8)
#define EPSV 1e-5f
#define WSCALE 268435456.0f          // 2^28 fixed-point weight scale
#define WINV   (1.0f / 268435456.0f)

// ---------------- scratch (device globals; zero-initialized at load) -------
// Invariant: every call leaves g_degcnt/g_bnsum/g_bnsq/g_scan_ctr all-zero
// (CLEAN tail in the final kernel), matching first-call zero-init. Everything
// else is fully rewritten every call (incl. g_edge pad slots, written by scan).
__device__ unsigned long long g_degcnt[NN]; // (cnt<<48) | fx28 weighted degree
__device__ float g_dinv[NN];
__device__ int   g_erank[EE];               // edge rank within its dst row
__device__ int   g_rowptr[NN + 1];          // padded exclusive prefix
__device__ unsigned long long g_edge[EEP];  // packed: (w_bits<<32) | src
__device__ __half g_h1[(size_t)NN * DF];    // dinv-scaled layer-1 features (fp16)
__device__ __half g_hb[(size_t)NN * DF];    // aggregated layer-1 output (fp16)
__device__ __half g_h2[(size_t)NN * DF];    // dinv-scaled layer-2 features (fp16)
__device__ float g_bnsum[DF];
__device__ float g_bnsq[DF];
__device__ int   g_part[128];
__device__ int   g_scan_ctr;

__device__ __forceinline__ unsigned long long pack_dc(float w) {
    return (1ULL << 48) | (unsigned long long)(fmaf(w, WSCALE, 0.5f));
}

// ---------------- edge pass 1: packed atomic per edge; record rank ---------
// The returned old cnt field (bits 48+) is this edge's rank within its dst.
// Exact: each add contributes exactly 1<<48; the fx28 weight sum stays below
// 2^40, so no carry ever reaches bit 48.
__global__ void k_edge_deg(const int* __restrict__ ei,
                           const float* __restrict__ w, int E) {
    int e8 = (blockIdx.x * blockDim.x + threadIdx.x) * 8;
    if (e8 + 7 < E) {
        int4   d0 = *(const int4*)&ei[E + e8];
        int4   d1 = *(const int4*)&ei[E + e8 + 4];
        float4 w0 = *(const float4*)&w[e8];
        float4 w1 = *(const float4*)&w[e8 + 4];
        int4 r0, r1;
        r0.x = (int)(atomicAdd(&g_degcnt[d0.x], pack_dc(w0.x)) >> 48);
        r0.y = (int)(atomicAdd(&g_degcnt[d0.y], pack_dc(w0.y)) >> 48);
        r0.z = (int)(atomicAdd(&g_degcnt[d0.z], pack_dc(w0.z)) >> 48);
        r0.w = (int)(atomicAdd(&g_degcnt[d0.w], pack_dc(w0.w)) >> 48);
        r1.x = (int)(atomicAdd(&g_degcnt[d1.x], pack_dc(w1.x)) >> 48);
        r1.y = (int)(atomicAdd(&g_degcnt[d1.y], pack_dc(w1.y)) >> 48);
        r1.z = (int)(atomicAdd(&g_degcnt[d1.z], pack_dc(w1.z)) >> 48);
        r1.w = (int)(atomicAdd(&g_degcnt[d1.w], pack_dc(w1.w)) >> 48);
        *(int4*)&g_erank[e8]     = r0;
        *(int4*)&g_erank[e8 + 4] = r1;
    } else {
        for (int e = e8; e < E; e++)
            g_erank[e] = (int)(atomicAdd(&g_degcnt[ei[E + e]],
                                         pack_dc(w[e])) >> 48);
    }
}

// ---------------- fused scan: dinv + padded prefix + pad-slot zeroing ------
__global__ void k_scan(int n, int nb) {
    __shared__ int s[1024];
    __shared__ int sp[128];
    int t = threadIdx.x;
    int i = blockIdx.x * 1024 + t;

    int cnt = 0, v = 0;
    if (i < n) {
        unsigned long long p = g_degcnt[i];
        cnt = (int)(p >> 48);
        float deg = (float)(long long)(p & 0xFFFFFFFFFFFFULL) * WINV;
        g_dinv[i] = rsqrtf(deg + 1.0f);        // +1 = self loop
        v = (cnt + 7) & ~7;                    // pad row to multiple of 8
    }

    s[t] = v;
    __syncthreads();
    for (int off = 512; off > 0; off >>= 1) {
        if (t < off) s[t] += s[t + off];
        __syncthreads();
    }
    if (t == 0) {
        g_part[blockIdx.x] = s[0];
        __threadfence();
        atomicAdd(&g_scan_ctr, 1);
    }
    __syncthreads();

    s[t] = v;
    __syncthreads();
    for (int off = 1; off < 1024; off <<= 1) {
        int a = (t >= off) ? s[t - off] : 0;
        __syncthreads();
        s[t] += a;
        __syncthreads();
    }

    if (t == 0) {
        while (atomicAdd(&g_scan_ctr, 0) < nb) { }
    }
    __syncthreads();

    if (t < 128) sp[t] = (t < nb) ? g_part[t] : 0;
    __syncthreads();
    #pragma unroll
    for (int off = 1; off < 128; off <<= 1) {
        int a = (t < 128 && t >= off) ? sp[t - off] : 0;
        __syncthreads();
        if (t < 128) sp[t] += a;
        __syncthreads();
    }

    int bp = (blockIdx.x > 0) ? sp[blockIdx.x - 1] : 0;
    if (i < n) {
        int p = bp + s[t] - v;                 // padded exclusive prefix
        g_rowptr[i] = p;
        for (int k = p + cnt; k < p + v; k++)  // zero-weight pad slots
            g_edge[k] = 0ULL;
    }
    if (i == n - 1) g_rowptr[n] = bp + s[t];
}

// ---------------- edge pass 2: fill CSR, NO atomics (rank precomputed) -----
__device__ __forceinline__ unsigned long long pack_edge(float w, int s) {
    return ((unsigned long long)__float_as_uint(w) << 32) |
           (unsigned long long)(unsigned)s;
}
__global__ void k_fill(const int* __restrict__ ei,
                       const float* __restrict__ w, int E) {
    int e4 = (blockIdx.x * blockDim.x + threadIdx.x) * 4;
    if (e4 + 3 < E) {
        int4   sv = *(const int4*)&ei[e4];
        int4   dv = *(const int4*)&ei[E + e4];
        float4 wv = *(const float4*)&w[e4];
        int4   rv = *(const int4*)&g_erank[e4];
        g_edge[g_rowptr[dv.x] + rv.x] = pack_edge(wv.x, sv.x);
        g_edge[g_rowptr[dv.y] + rv.y] = pack_edge(wv.y, sv.y);
        g_edge[g_rowptr[dv.z] + rv.z] = pack_edge(wv.z, sv.z);
        g_edge[g_rowptr[dv.w] + rv.w] = pack_edge(wv.w, sv.w);
    } else {
        for (int e = e4; e < E; e++)
            g_edge[g_rowptr[ei[E + e]] + g_erank[e]] = pack_edge(w[e], ei[e]);
    }
}

// ---------------- GEMM (tensor cores): Yh = dinv .* (f(X) @ W), fp16 out ---
template <bool BN, bool HALF_IN>
__global__ void __launch_bounds__(256) k_gemm(const void* __restrict__ Xv,
                                              const float* __restrict__ W,
                                              __half* __restrict__ Yh, int n,
                                              const float* __restrict__ gamma,
                                              const float* __restrict__ beta,
                                              float invn) {
    __shared__ __align__(16) char usm[128 * 68 * 4];     // 34 KB union A/C
    __shared__ __align__(16) __half sB[64][72];          // 9 KB W fp16
    __shared__ float sBNa[64], sBNc[64];
    __half (*sA)[72] = (__half(*)[72])usm;
    float  (*uC)[68] = (float(*)[68])usm;

    int tid  = threadIdx.x;
    int w    = tid >> 5;
    int lane = tid & 31;
    int rbase = blockIdx.x * 128;

    if (BN && tid < 64) {
        float mu   = g_bnsum[tid] * invn;
        float var  = g_bnsq[tid] * invn - mu * mu;
        float a    = gamma[tid] * rsqrtf(var + EPSV);
        sBNa[tid] = a;
        sBNc[tid] = beta[tid] - mu * a;
    }
    for (int idx = tid; idx < 64 * 16; idx += 256) {
        int r = idx >> 4, c4 = idx & 15;
        float4 v = ((const float4*)W)[idx];
        __half2 h0 = __floats2half2_rn(v.x, v.y);
        __half2 h1 = __floats2half2_rn(v.z, v.w);
        *(__half2*)&sB[r][c4 * 4]     = h0;
        *(__half2*)&sB[r][c4 * 4 + 2] = h1;
    }
    if (BN) __syncthreads();

    if (HALF_IN) {
        const __half* X = (const __half*)Xv;
        for (int idx = tid; idx < 128 * 8; idx += 256) {
            int r = idx >> 3, c8 = idx & 7;
            int gr = rbase + r;
            uint4 v = (gr < n) ? ((const uint4*)X)[(size_t)gr * 8 + c8]
                               : make_uint4(0, 0, 0, 0);
            if (BN) {
                #pragma unroll
                for (int q = 0; q < 4; q++) {
                    unsigned lo = (&v.x)[q];
                    float2 f = __half22float2(*(const __half2*)&lo);
                    int c = c8 * 8 + q * 2;
                    f.x = fmaxf(fmaf(sBNa[c],     f.x, sBNc[c]),     0.f);
                    f.y = fmaxf(fmaf(sBNa[c + 1], f.y, sBNc[c + 1]), 0.f);
                    __half2 h = __floats2half2_rn(f.x, f.y);
                    (&v.x)[q] = *(unsigned*)&h;
                }
            }
            *(uint4*)&sA[r][c8 * 8] = v;
        }
    } else {
        const float* X = (const float*)Xv;
        for (int idx = tid; idx < 128 * 16; idx += 256) {
            int r = idx >> 4, c4 = idx & 15;
            int gr = rbase + r;
            float4 v = (gr < n) ? ((const float4*)X)[(size_t)gr * 16 + c4]
                                : make_float4(0.f, 0.f, 0.f, 0.f);
            if (BN) {
                int c = c4 * 4;
                v.x = fmaxf(fmaf(sBNa[c],     v.x, sBNc[c]),     0.f);
                v.y = fmaxf(fmaf(sBNa[c + 1], v.y, sBNc[c + 1]), 0.f);
                v.z = fmaxf(fmaf(sBNa[c + 2], v.z, sBNc[c + 2]), 0.f);
                v.w = fmaxf(fmaf(sBNa[c + 3], v.w, sBNc[c + 3]), 0.f);
            }
            __half2 h0 = __floats2half2_rn(v.x, v.y);
            __half2 h1 = __floats2half2_rn(v.z, v.w);
            *(__half2*)&sA[r][c4 * 4]     = h0;
            *(__half2*)&sA[r][c4 * 4 + 2] = h1;
        }
    }
    __syncthreads();

    wmma::fragment<wmma::matrix_a, 16, 16, 16, __half, wmma::row_major> af[4];
    #pragma unroll
    for (int kt = 0; kt < 4; kt++)
        wmma::load_matrix_sync(af[kt], &sA[w * 16][kt * 16], 72);
    __syncthreads();   // all A frags resident; usm may now be reused as C

    #pragma unroll
    for (int nt = 0; nt < 4; nt++) {
        wmma::fragment<wmma::accumulator, 16, 16, 16, float> cf;
        wmma::fill_fragment(cf, 0.0f);
        #pragma unroll
        for (int kt = 0; kt < 4; kt++) {
            wmma::fragment<wmma::matrix_b, 16, 16, 16, __half, wmma::row_major> bf;
            wmma::load_matrix_sync(bf, &sB[kt * 16][nt * 16], 72);
            wmma::mma_sync(cf, af[kt], bf, cf);
        }
        wmma::store_matrix_sync(&uC[w * 16][nt * 16], cf, 68, wmma::mem_row_major);
    }
    __syncwarp();

    int rl = lane & 15;
    int ch = lane >> 4;
    int r  = rbase + w * 16 + rl;
    if (r < n) {
        float dv = g_dinv[r];
        const float* crow = &uC[w * 16 + rl][ch * 32];
        uint4* dst = (uint4*)(Yh + (size_t)r * 64 + ch * 32);
        #pragma unroll
        for (int g = 0; g < 4; g++) {
            __half2 h0 = __floats2half2_rn(crow[8*g + 0] * dv, crow[8*g + 1] * dv);
            __half2 h1 = __floats2half2_rn(crow[8*g + 2] * dv, crow[8*g + 3] * dv);
            __half2 h2 = __floats2half2_rn(crow[8*g + 4] * dv, crow[8*g + 5] * dv);
            __half2 h3 = __floats2half2_rn(crow[8*g + 6] * dv, crow[8*g + 7] * dv);
            uint4 st;
            st.x = *(unsigned*)&h0; st.y = *(unsigned*)&h1;
            st.z = *(unsigned*)&h2; st.w = *(unsigned*)&h3;
            dst[g] = st;
        }
    }
}

// ---------------- aggregation: 8 lanes/node, 8 feats (16B fp16) per lane ---
// out[i] = dinv[i] * ( H'[i] + sum_e w_e * H'[src_e] ) + bias   (fp32 accum)
template <bool STATS, bool CLEAN, bool HALF_OUT>
__global__ void __launch_bounds__(256, 3) k_agg(const __half* __restrict__ H,
                                                const float* __restrict__ bias,
                                                void* __restrict__ outv, int n) {
    int tid = threadIdx.x;
    int sub = tid >> 3;         // 0..31 node slot
    int l8  = tid & 7;          // feature group (8 halves = 16B)
    int i   = blockIdx.x * 32 + sub;

    float acc[8];
    #pragma unroll
    for (int k = 0; k < 8; k++) acc[k] = 0.0f;

    if (i < n) {
        {   // self term (weight 1 in the dinv-scaled domain)
            uint4 u = ((const uint4*)(H + (size_t)i * 64))[l8];
            float2 f0 = __half22float2(*(const __half2*)&u.x);
            float2 f1 = __half22float2(*(const __half2*)&u.y);
            float2 f2 = __half22float2(*(const __half2*)&u.z);
            float2 f3 = __half22float2(*(const __half2*)&u.w);
            acc[0] = f0.x; acc[1] = f0.y; acc[2] = f1.x; acc[3] = f1.y;
            acc[4] = f2.x; acc[5] = f2.y; acc[6] = f3.x; acc[7] = f3.y;
        }

        int e   = g_rowptr[i];
        int end = g_rowptr[i + 1];   // e, end multiples of 8

        for (int base = e; base < end; base += 8) {
            const ulonglong2* pp = (const ulonglong2*)(g_edge + base);
            ulonglong2 q0 = pp[0], q1 = pp[1], q2 = pp[2], q3 = pp[3];
            unsigned long long p[8] = { q0.x, q0.y, q1.x, q1.y,
                                        q2.x, q2.y, q3.x, q3.y };
            uint4 u[8];
            #pragma unroll
            for (int j = 0; j < 8; j++)
                u[j] = ((const uint4*)(H + (size_t)(unsigned)p[j] * 64))[l8];
            #pragma unroll
            for (int j = 0; j < 8; j++) {
                float wj = __uint_as_float((unsigned)(p[j] >> 32));
                #pragma unroll
                for (int q = 0; q < 4; q++) {
                    unsigned lo = (&u[j].x)[q];
                    float2 f = __half22float2(*(const __half2*)&lo);
                    acc[2*q]   = fmaf(wj, f.x, acc[2*q]);
                    acc[2*q+1] = fmaf(wj, f.y, acc[2*q+1]);
                }
            }
        }

        float dv = g_dinv[i];
        const float4* B4 = (const float4*)bias;
        float4 b0 = B4[l8 * 2], b1 = B4[l8 * 2 + 1];
        #pragma unroll
        for (int k = 0; k < 4; k++) acc[k]     = fmaf(dv, acc[k],     (&b0.x)[k]);
        #pragma unroll
        for (int k = 0; k < 4; k++) acc[k + 4] = fmaf(dv, acc[k + 4], (&b1.x)[k]);

        if (HALF_OUT) {
            __half* out = (__half*)outv;
            __half2 h0 = __floats2half2_rn(acc[0], acc[1]);
            __half2 h1 = __floats2half2_rn(acc[2], acc[3]);
            __half2 h2 = __floats2half2_rn(acc[4], acc[5]);
            __half2 h3 = __floats2half2_rn(acc[6], acc[7]);
            uint4 st;
            st.x = *(unsigned*)&h0; st.y = *(unsigned*)&h1;
            st.z = *(unsigned*)&h2; st.w = *(unsigned*)&h3;
            ((uint4*)(out + (size_t)i * 64))[l8] = st;
        } else {
            float* out = (float*)outv;
            float4* O4 = (float4*)(out + (size_t)i * 64);
            O4[l8 * 2]     = make_float4(acc[0], acc[1], acc[2], acc[3]);
            O4[l8 * 2 + 1] = make_float4(acc[4], acc[5], acc[6], acc[7]);
        }
    } else {
        #pragma unroll
        for (int k = 0; k < 8; k++) acc[k] = 0.0f;
    }

    if (STATS) {
        __shared__ __align__(16) float sacc[32][68];
        float4* row = (float4*)&sacc[sub][l8 * 8];
        row[0] = make_float4(acc[0], acc[1], acc[2], acc[3]);
        row[1] = make_float4(acc[4], acc[5], acc[6], acc[7]);
        __syncthreads();
        if (tid < 64) {
            float s = 0.f, q = 0.f;
            #pragma unroll
            for (int k = 0; k < 32; k++) {
                float v = sacc[k][tid];
                s += v;
                q += v * v;
            }
            atomicAdd(&g_bnsum[tid], s);
            atomicAdd(&g_bnsq[tid],  q);
        }
    }

    if (CLEAN) {
        int g = blockIdx.x * 256 + tid;
        if (g < n) g_degcnt[g] = 0ULL;
        if (g < DF) { g_bnsum[g] = 0.0f; g_bnsq[g] = 0.0f; }
        if (g == 0) g_scan_ctr = 0;
    }
}

// ---------------------------------------------------------------------------
// Fork resources: created once on the first (uncaptured correctness) call.
static cudaStream_t g_s2  = nullptr;
static cudaEvent_t  g_ev1 = nullptr;
static cudaEvent_t  g_ev2 = nullptr;

extern "C" void kernel_launch(void* const* d_in, const int* in_sizes, int n_in,
                              void* d_out, int out_size) {
    const float* x     = (const float*)d_in[0];
    const int*   ei    = (const int*)d_in[1];
    const float* ew    = (const float*)d_in[2];
    const float* W1    = (const float*)d_in[3];
    const float* b1    = (const float*)d_in[4];
    const float* gamma = (const float*)d_in[5];
    const float* beta  = (const float*)d_in[6];
    const float* W2    = (const float*)d_in[7];
    const float* b2    = (const float*)d_in[8];

    int N = in_sizes[0] / DF;
    int E = in_sizes[2];
    if (N > NN || E > EE) return;

    if (!g_s2) {
        cudaStreamCreateWithFlags(&g_s2, cudaStreamNonBlocking);
        cudaEventCreateWithFlags(&g_ev1, cudaEventDisableTiming);
        cudaEventCreateWithFlags(&g_ev2, cudaEventDisableTiming);
    }

    __half *p_h1, *p_hb, *p_h2;
    cudaGetSymbolAddress((void**)&p_h1, g_h1);
    cudaGetSymbolAddress((void**)&p_hb, g_hb);
    cudaGetSymbolAddress((void**)&p_h2, g_h2);

    int nb = (N + 1023) / 1024;
    float invn = 1.0f / (float)N;

    // ---- CSR build chain (stream 0) ----
    k_edge_deg<<<(E / 8 + 255) / 256 + 1, 256>>>(ei, ew, E);
    k_scan<<<nb, 1024>>>(N, nb);

    // ---- fork: GEMM1 (needs only dinv) runs concurrent with fill ----
    cudaEventRecord(g_ev1, 0);
    cudaStreamWaitEvent(g_s2, g_ev1, 0);
    k_gemm<false, false><<<(N + 127) / 128, 256, 0, g_s2>>>(
        x, W1, p_h1, N, nullptr, nullptr, 0.f);
    cudaEventRecord(g_ev2, g_s2);

    k_fill<<<(E / 4 + 255) / 256 + 1, 256>>>(ei, ew, E);

    cudaStreamWaitEvent(0, g_ev2, 0);   // join before agg1

    // ---- serial tail (data-dependent) ----
    k_agg<true, false, true><<<(N + 31) / 32, 256>>>(p_h1, b1, p_hb, N);
    k_gemm<true, true><<<(N + 127) / 128, 256>>>(
        p_hb, W2, p_h2, N, gamma, beta, invn);
    k_agg<false, true, false><<<(N + 31) / 32, 256>>>(p_h2, b2, d_out, N);
}